// round 4
// baseline (speedup 1.0000x reference)
#include <cuda_runtime.h>

// StatsQuantizer 4-bit fake-quant, 8192x8192 fp32.
// Forward math (gradient-only terms eliminated):
//   s    = 2 * mean(|w_row|)          (per row, axis=1)
//   c    = clamp(w/s, -clip/2, clip/2 - 1e-6)
//   out  = s * ((rint(c*8 - 0.5) + 0.5) / 8)
//
// One CTA (256 thr) per row, 8 consecutive LDG.128 per thread (MLP=8).
// Hybrid staging across the barrier: 6 float4 -> smem (24 KB), 2 -> regs.
// launch_bounds(256,8) caps regs at 32 -> 8 CTAs/SM -> 100% occupancy
// AND full per-thread MLP. Streaming hints: one touch each way.

#define ROWS 8192
#define COLS 8192
#define TPB  256
#define V4_TOTAL 8            // float4 per thread
#define V4_SMEM  6            // staged in shared memory
#define V4_REG   (V4_TOTAL - V4_SMEM)

__global__ __launch_bounds__(TPB, 8)
void stats_quant_kernel(const float* __restrict__ w,
                        const float* __restrict__ clip_val,
                        float* __restrict__ out) {
    __shared__ float4 srow[V4_SMEM * TPB];   // 24 KB
    __shared__ float warp_sums[TPB / 32];
    __shared__ float s_scale;

    const int row = blockIdx.x;
    const float4* __restrict__ wrow =
        reinterpret_cast<const float4*>(w + (size_t)row * COLS);
    float4* __restrict__ orow =
        reinterpret_cast<float4*>(out + (size_t)row * COLS);

    float asum = 0.0f;

    // ---- smem-staged portion: load, accumulate, park in smem ----
#pragma unroll
    for (int i = 0; i < V4_SMEM; i++) {
        const int idx = threadIdx.x + i * TPB;
        float4 t = __ldcs(&wrow[idx]);
        asum += fabsf(t.x) + fabsf(t.y) + fabsf(t.z) + fabsf(t.w);
        srow[idx] = t;
    }

    // ---- register-held portion ----
    float4 vr[V4_REG];
#pragma unroll
    for (int i = 0; i < V4_REG; i++) {
        vr[i] = __ldcs(&wrow[threadIdx.x + (V4_SMEM + i) * TPB]);
        asum += fabsf(vr[i].x) + fabsf(vr[i].y) + fabsf(vr[i].z) + fabsf(vr[i].w);
    }

    // ---- Block reduction: warp shfl then cross-warp ----
#pragma unroll
    for (int off = 16; off > 0; off >>= 1)
        asum += __shfl_xor_sync(0xffffffffu, asum, off);
    if ((threadIdx.x & 31) == 0)
        warp_sums[threadIdx.x >> 5] = asum;
    __syncthreads();
    if (threadIdx.x == 0) {
        float t = 0.0f;
#pragma unroll
        for (int i = 0; i < TPB / 32; i++) t += warp_sums[i];
        s_scale = t * (1.0f / 4096.0f);      // s = 2*mean(|w|) = t/4096
    }
    __syncthreads();

    const float s     = s_scale;
    const float invs  = 1.0f / s;
    const float hc    = 0.5f * clip_val[0];
    const float lo    = -hc;
    const float hi    = hc - 1e-6f;
    const float sdiv8 = s * 0.125f;

    // ---- Quantize: smem part then register part, stream out ----
#pragma unroll
    for (int i = 0; i < V4_SMEM; i++) {
        const int idx = threadIdx.x + i * TPB;
        float4 v = srow[idx];
        float4 r;
        float* pv = &v.x;
        float* pr = &r.x;
#pragma unroll
        for (int j = 0; j < 4; j++) {
            float c  = fminf(fmaxf(pv[j] * invs, lo), hi);
            float b4 = fmaf(c, 8.0f, -0.5f);
            pr[j]    = (rintf(b4) + 0.5f) * sdiv8;
        }
        __stcs(&orow[idx], r);
    }
#pragma unroll
    for (int i = 0; i < V4_REG; i++) {
        float4 r;
        float* pv = &vr[i].x;
        float* pr = &r.x;
#pragma unroll
        for (int j = 0; j < 4; j++) {
            float c  = fminf(fmaxf(pv[j] * invs, lo), hi);
            float b4 = fmaf(c, 8.0f, -0.5f);
            pr[j]    = (rintf(b4) + 0.5f) * sdiv8;
        }
        __stcs(&orow[threadIdx.x + (V4_SMEM + i) * TPB], r);
    }
}

extern "C" void kernel_launch(void* const* d_in, const int* in_sizes, int n_in,
                              void* d_out, int out_size) {
    const float* weight   = (const float*)d_in[0];
    const float* clip_val = (const float*)d_in[1];
    float* out            = (float*)d_out;
    (void)in_sizes; (void)n_in; (void)out_size;

    stats_quant_kernel<<<ROWS, TPB>>>(weight, clip_val, out);
}

// round 5
// speedup vs baseline: 1.1243x; 1.1243x over previous
#include <cuda_runtime.h>
#include <cstdint>

// StatsQuantizer 4-bit fake-quant, 8192x8192 fp32.
//   s   = 2 * mean(|w_row|)
//   c   = clamp(w/s, -clip/2, clip/2 - 1e-6)
//   out = s * ((rint(c*8 - 0.5) + 0.5) / 8)
//
// One CTA per row. The read side is a single cp.async.bulk (TMA) of the
// 32 KB row into smem: in-flight read bytes are no longer limited by
// per-thread LDG registers (the R3/R4 failure mode). Compute reads smem
// twice (reduce pass, quantize pass) so no payload regs cross the barrier.
// Writes are streaming STG.128.

#define ROWS 8192
#define COLS 8192
#define TPB  256
#define ROW_BYTES (COLS * 4)           // 32768
#define V4 (COLS / 4 / TPB)            // 8 float4 per thread

__global__ __launch_bounds__(TPB)
void stats_quant_kernel(const float* __restrict__ w,
                        const float* __restrict__ clip_val,
                        float* __restrict__ out) {
    __shared__ alignas(128) float4 srow[COLS / 4];   // 32 KB
    __shared__ uint64_t mbar;
    __shared__ float warp_sums[TPB / 32];
    __shared__ float s_scale;

    const int row = blockIdx.x;
    const float* grow = w + (size_t)row * COLS;
    float4* __restrict__ orow =
        reinterpret_cast<float4*>(out + (size_t)row * COLS);

    const uint32_t smem_addr = (uint32_t)__cvta_generic_to_shared(srow);
    const uint32_t mbar_addr = (uint32_t)__cvta_generic_to_shared(&mbar);

    // ---- init mbarrier (1 arrival), make visible to async proxy ----
    if (threadIdx.x == 0) {
        asm volatile("mbarrier.init.shared.b64 [%0], %1;"
                     :: "r"(mbar_addr), "r"(1) : "memory");
        asm volatile("fence.proxy.async.shared::cta;" ::: "memory");
    }
    __syncthreads();

    // ---- one bulk TMA copy: 32 KB row global -> smem ----
    if (threadIdx.x == 0) {
        asm volatile("mbarrier.arrive.expect_tx.shared.b64 _, [%0], %1;"
                     :: "r"(mbar_addr), "r"(ROW_BYTES) : "memory");
        asm volatile("cp.async.bulk.shared::cluster.global.mbarrier::complete_tx::bytes "
                     "[%0], [%1], %2, [%3];"
                     :: "r"(smem_addr), "l"(grow), "r"(ROW_BYTES), "r"(mbar_addr)
                     : "memory");
    }

    // ---- all threads wait for phase 0 completion ----
    {
        uint32_t done;
        asm volatile(
            "{\n\t.reg .pred p;\n\t"
            "mbarrier.try_wait.parity.acquire.cta.shared::cta.b64 p, [%1], 0;\n\t"
            "selp.b32 %0, 1, 0, p;\n\t}"
            : "=r"(done) : "r"(mbar_addr) : "memory");
        if (!done) {
            asm volatile(
                "{\n\t.reg .pred P1;\n\t"
                "WAIT_LOOP_%=:\n\t"
                "mbarrier.try_wait.parity.acquire.cta.shared::cta.b64 P1, [%0], 0, 0x989680;\n\t"
                "@P1 bra.uni WAIT_DONE_%=;\n\t"
                "bra.uni WAIT_LOOP_%=;\n\t"
                "WAIT_DONE_%=:\n\t}"
                :: "r"(mbar_addr) : "memory");
        }
    }

    // ---- pass 1: |w| sum from smem (values discarded, no payload regs) ----
    float asum = 0.0f;
#pragma unroll
    for (int i = 0; i < V4; i++) {
        float4 t = srow[threadIdx.x + i * TPB];
        asum += fabsf(t.x) + fabsf(t.y) + fabsf(t.z) + fabsf(t.w);
    }

    // ---- block reduction ----
#pragma unroll
    for (int off = 16; off > 0; off >>= 1)
        asum += __shfl_xor_sync(0xffffffffu, asum, off);
    if ((threadIdx.x & 31) == 0)
        warp_sums[threadIdx.x >> 5] = asum;
    __syncthreads();
    if (threadIdx.x == 0) {
        float t = 0.0f;
#pragma unroll
        for (int i = 0; i < TPB / 32; i++) t += warp_sums[i];
        s_scale = t * (1.0f / 4096.0f);   // s = 2*mean(|w|) = t/4096
    }
    __syncthreads();

    const float s     = s_scale;
    const float invs  = 1.0f / s;
    const float hc    = 0.5f * clip_val[0];
    const float lo    = -hc;
    const float hi    = hc - 1e-6f;
    const float sdiv8 = s * 0.125f;

    // ---- pass 2: quantize from smem, stream out ----
#pragma unroll
    for (int i = 0; i < V4; i++) {
        const int idx = threadIdx.x + i * TPB;
        float4 v = srow[idx];
        float4 r;
        float* pv = &v.x;
        float* pr = &r.x;
#pragma unroll
        for (int j = 0; j < 4; j++) {
            float c  = fminf(fmaxf(pv[j] * invs, lo), hi);
            float b4 = fmaf(c, 8.0f, -0.5f);
            pr[j]    = (rintf(b4) + 0.5f) * sdiv8;
        }
        __stcs(&orow[idx], r);
    }
}

extern "C" void kernel_launch(void* const* d_in, const int* in_sizes, int n_in,
                              void* d_out, int out_size) {
    const float* weight   = (const float*)d_in[0];
    const float* clip_val = (const float*)d_in[1];
    float* out            = (float*)d_out;
    (void)in_sizes; (void)n_in; (void)out_size;

    stats_quant_kernel<<<ROWS, TPB>>>(weight, clip_val, out);
}